// round 1
// baseline (speedup 1.0000x reference)
#include <cuda_runtime.h>
#include <cstdint>

// Problem constants
#define BS_    64
#define SEQ_   1024
#define D_     800
#define NSLOT_ 64
#define NLAB_  72
#define NPOOL_ (BS_ * NSLOT_)   // 4096
#define D4_    (D_ / 4)         // 200

// Scratch for pooled vectors (allocation-free rule: __device__ global)
__device__ float g_pool[NPOOL_ * D_];

// ---------------------------------------------------------------------------
// f32x2 packed-math helpers (sm_100+): 2x fp32 FMA throughput per instruction
// ---------------------------------------------------------------------------
__device__ __forceinline__ unsigned long long splat2(float x) {
    unsigned long long r;
    asm("mov.b64 %0, {%1, %1};" : "=l"(r) : "f"(x));
    return r;
}
__device__ __forceinline__ void fma2(unsigned long long& d,
                                     unsigned long long a,
                                     unsigned long long b) {
    asm("fma.rn.f32x2 %0, %1, %2, %0;" : "+l"(d) : "l"(a), "l"(b));
}
__device__ __forceinline__ void unpack2(unsigned long long v, float& lo, float& hi) {
    asm("mov.b64 {%0, %1}, %2;" : "=f"(lo), "=f"(hi) : "l"(v));
}

// ---------------------------------------------------------------------------
// Kernel 1: ragged span mean pooling.
// One block per (batch, slot). 200 active threads each own one float4 lane of
// the 800-dim row; accumulate over the (<=8)-row span, scale by 1/count.
// ---------------------------------------------------------------------------
__global__ __launch_bounds__(256) void pool_kernel(
    const float* __restrict__ hs,
    const int*   __restrict__ begins,
    const int*   __restrict__ lens)
{
    const int slot = blockIdx.x;           // 0..4095
    const int b    = slot >> 6;            // slot / 64
    const int begin = begins[slot];
    const int len   = lens[slot];          // inclusive span => count = len+1
    const float inv = 1.0f / (float)(len + 1);

    const int t = threadIdx.x;
    if (t >= D4_) return;

    const float4* __restrict__ row =
        reinterpret_cast<const float4*>(hs) + (size_t)(b * SEQ_ + begin) * D4_;

    float4 acc = row[t];
    #pragma unroll 7
    for (int r = 1; r <= len; ++r) {
        float4 v = row[(size_t)r * D4_ + t];
        acc.x += v.x; acc.y += v.y; acc.z += v.z; acc.w += v.w;
    }
    acc.x *= inv; acc.y *= inv; acc.z *= inv; acc.w *= inv;
    reinterpret_cast<float4*>(g_pool)[(size_t)slot * D4_ + t] = acc;
}

// ---------------------------------------------------------------------------
// Kernel 2: logits = pool (4096 x 800) @ W (800 x 72) + bias, fp32.
// Block tile: BM=32 rows x full N=72, K chunked by BK=80.
// 288 threads = 16 (m-groups of 2) x 18 (n-groups of 4); 2x4 register tile,
// inner product via packed f32x2 FMAs.
// ---------------------------------------------------------------------------
#define BM_  32
#define BK_  80
#define ASTRIDE_ 34   // k-major A tile stride (keeps float2 loads 8B-aligned,
                      // conflict-free across the 16 m-groups)

__global__ __launch_bounds__(288) void gemm_kernel(
    const float* __restrict__ W,     // (800, 72) row-major
    const float* __restrict__ bias,  // (72,)
    float*       __restrict__ out)   // (4096, 72) row-major
{
    __shared__ float As[BK_ * ASTRIDE_];  // [k][m], stride 34
    __shared__ float Bs[BK_ * NLAB_];     // [k][n], stride 72

    const int tid   = threadIdx.x;
    const int tm    = tid & 15;     // 0..15  -> rows tm*2, tm*2+1
    const int tn    = tid >> 4;     // 0..17  -> cols tn*4 .. tn*4+3
    const int mBase = blockIdx.x * BM_;

    unsigned long long acc[4];      // [m0|n01, m0|n23, m1|n01, m1|n23]
    acc[0] = acc[1] = acc[2] = acc[3] = 0ull;

    const float4* __restrict__ pool4 = reinterpret_cast<const float4*>(g_pool);
    const float4* __restrict__ W4    = reinterpret_cast<const float4*>(W);

    for (int kc = 0; kc < D_; kc += BK_) {
        // --- load A tile: 32 rows x 80 cols -> As[k][m] (transposed) ---
        #pragma unroll
        for (int idx = tid; idx < BM_ * (BK_ / 4); idx += 288) {
            int m  = idx / (BK_ / 4);       // 0..31
            int kq = idx % (BK_ / 4);       // 0..19
            float4 v = pool4[(size_t)(mBase + m) * D4_ + (kc >> 2) + kq];
            int k = kq * 4;
            As[(k + 0) * ASTRIDE_ + m] = v.x;
            As[(k + 1) * ASTRIDE_ + m] = v.y;
            As[(k + 2) * ASTRIDE_ + m] = v.z;
            As[(k + 3) * ASTRIDE_ + m] = v.w;
        }
        // --- load B tile: 80 rows x 72 cols, contiguous float4 ---
        #pragma unroll
        for (int idx = tid; idx < BK_ * (NLAB_ / 4); idx += 288) {
            int k  = idx / (NLAB_ / 4);     // 0..79
            int nq = idx % (NLAB_ / 4);     // 0..17
            reinterpret_cast<float4*>(Bs)[k * (NLAB_ / 4) + nq] =
                W4[(size_t)(kc + k) * (NLAB_ / 4) + nq];
        }
        __syncthreads();

        #pragma unroll 16
        for (int k = 0; k < BK_; ++k) {
            // A: two consecutive rows' values at this k (8B-aligned, stride 34)
            float2 a = *reinterpret_cast<const float2*>(&As[k * ASTRIDE_ + tm * 2]);
            // B: 4 consecutive labels at this k, as two packed f32x2
            const unsigned long long* bp =
                reinterpret_cast<const unsigned long long*>(&Bs[k * NLAB_ + tn * 4]);
            unsigned long long b01 = bp[0];
            unsigned long long b23 = bp[1];
            unsigned long long a0 = splat2(a.x);
            unsigned long long a1 = splat2(a.y);
            fma2(acc[0], a0, b01);
            fma2(acc[1], a0, b23);
            fma2(acc[2], a1, b01);
            fma2(acc[3], a1, b23);
        }
        __syncthreads();
    }

    // --- epilogue: add bias, store 2 rows x 4 cols as float4 ---
    float4 bv = reinterpret_cast<const float4*>(bias)[tn];
    float r00, r01, r02, r03, r10, r11, r12, r13;
    unpack2(acc[0], r00, r01);
    unpack2(acc[1], r02, r03);
    unpack2(acc[2], r10, r11);
    unpack2(acc[3], r12, r13);

    const int row0 = mBase + tm * 2;
    float4 o0 = make_float4(r00 + bv.x, r01 + bv.y, r02 + bv.z, r03 + bv.w);
    float4 o1 = make_float4(r10 + bv.x, r11 + bv.y, r12 + bv.z, r13 + bv.w);
    reinterpret_cast<float4*>(out)[(size_t)row0 * (NLAB_ / 4) + tn]       = o0;
    reinterpret_cast<float4*>(out)[(size_t)(row0 + 1) * (NLAB_ / 4) + tn] = o1;
}

// ---------------------------------------------------------------------------
// Launch wrapper
// Inputs (metadata order): batch_hs f32[64*1024*800], slot_begins i32[64*64],
// slot_lens i32[64*64], W_clf f32[800*72], b_clf f32[72].
// Output: f32[64*64*72].
// ---------------------------------------------------------------------------
extern "C" void kernel_launch(void* const* d_in, const int* in_sizes, int n_in,
                              void* d_out, int out_size)
{
    const float* hs     = (const float*)d_in[0];
    const int*   begins = (const int*)  d_in[1];
    const int*   lens   = (const int*)  d_in[2];
    const float* W      = (const float*)d_in[3];
    const float* bias   = (const float*)d_in[4];
    float*       out    = (float*)d_out;

    pool_kernel<<<NPOOL_, 256>>>(hs, begins, lens);
    gemm_kernel<<<NPOOL_ / BM_, 288>>>(W, bias, out);
}

// round 2
// speedup vs baseline: 1.2308x; 1.2308x over previous
#include <cuda_runtime.h>
#include <cstdint>

// Problem constants
#define BS_    64
#define SEQ_   1024
#define D_     800
#define NSLOT_ 64
#define NLAB_  72
#define NPOOL_ (BS_ * NSLOT_)   // 4096
#define D4_    (D_ / 4)         // 200
#define D2_    (D_ / 2)         // 400

// Scratch for pooled vectors (allocation-free rule: __device__ global)
__device__ float g_pool[NPOOL_ * D_];

// ---------------------------------------------------------------------------
// f32x2 packed-math helpers (sm_100+)
// ---------------------------------------------------------------------------
__device__ __forceinline__ unsigned long long splat2(float x) {
    unsigned long long r;
    asm("mov.b64 %0, {%1, %1};" : "=l"(r) : "f"(x));
    return r;
}
__device__ __forceinline__ void fma2(unsigned long long& d,
                                     unsigned long long a,
                                     unsigned long long b) {
    asm("fma.rn.f32x2 %0, %1, %2, %0;" : "+l"(d) : "l"(a), "l"(b));
}
__device__ __forceinline__ void unpack2(unsigned long long v, float& lo, float& hi) {
    asm("mov.b64 {%0, %1}, %2;" : "=f"(lo), "=f"(hi) : "l"(v));
}

// ---------------------------------------------------------------------------
// Kernel 1: ragged span mean pooling (unchanged — near DRAM floor).
// ---------------------------------------------------------------------------
__global__ __launch_bounds__(256) void pool_kernel(
    const float* __restrict__ hs,
    const int*   __restrict__ begins,
    const int*   __restrict__ lens)
{
    const int slot = blockIdx.x;           // 0..4095
    const int b    = slot >> 6;
    const int begin = begins[slot];
    const int len   = lens[slot];          // count = len+1
    const float inv = 1.0f / (float)(len + 1);

    const int t = threadIdx.x;
    if (t >= D4_) return;

    const float4* __restrict__ row =
        reinterpret_cast<const float4*>(hs) + (size_t)(b * SEQ_ + begin) * D4_;

    float4 acc = row[t];
    #pragma unroll 7
    for (int r = 1; r <= len; ++r) {
        float4 v = row[(size_t)r * D4_ + t];
        acc.x += v.x; acc.y += v.y; acc.z += v.z; acc.w += v.w;
    }
    acc.x *= inv; acc.y *= inv; acc.z *= inv; acc.w *= inv;
    reinterpret_cast<float4*>(g_pool)[(size_t)slot * D4_ + t] = acc;
}

// ---------------------------------------------------------------------------
// Kernel 2: logits = pool (4096 x 800) @ W (800 x 72) + bias, fp32.
//
// Block: 256 threads = 8 independent warp-slices. Each slice owns the SAME
// 32x72 output tile but a DISTINCT K-range of 100 (2 chunks of 50), with
// private smem A/B buffers -> no block-wide barriers in the mainloop.
// Per warp: thread grid 4(m-groups) x 8(n-groups); thread tile 8m x 9n,
// m-paired f32x2 FMAs (36 fma2 = 72 FMA per k per thread).
// Epilogue: 8-way cross-slice reduction through (reused) smem.
// ---------------------------------------------------------------------------
#define BM_      32
#define KSLICE_  100       // K per warp-slice (8 slices x 100 = 800)
#define BKC_     50        // chunk within a slice (2 chunks)
#define ASTRIDE_ 34        // [k][m] A-tile stride (even => 8B-aligned m-pairs)
#define SL_B_FLOATS_ (BKC_ * NLAB_)              // 3600
#define SL_A_FLOATS_ (BKC_ * ASTRIDE_)           // 1700
#define SL_STRIDE_   (SL_B_FLOATS_ + SL_A_FLOATS_ + 4)  // 5304 floats (16B-mult)
#define SMEM_BYTES_  (8 * SL_STRIDE_ * 4)        // 169728 B
#define RED_FLOATS_  (BM_ * NLAB_)               // 2304 per slice

__global__ __launch_bounds__(256, 1) void gemm_kernel(
    const float* __restrict__ W,     // (800, 72) row-major
    const float* __restrict__ bias,  // (72,)
    float*       __restrict__ out)   // (4096, 72) row-major
{
    extern __shared__ float smem[];

    const int tid   = threadIdx.x;
    const int slice = tid >> 5;          // warp id, 0..7
    const int lane  = tid & 31;
    const int tm    = lane >> 3;         // 0..3  -> rows tm*8 .. tm*8+7
    const int tn    = lane & 7;          // 0..7  -> cols tn*9 .. tn*9+8
    const int mBase = blockIdx.x * BM_;

    float* Bs = smem + slice * SL_STRIDE_;            // [50][72]
    float* As = Bs + SL_B_FLOATS_;                    // [50][34] (k-major)

    unsigned long long acc[36];          // [mp(4)][n(9)], each = rows (2mp,2mp+1)
    #pragma unroll
    for (int i = 0; i < 36; ++i) acc[i] = 0ull;

    const float2* __restrict__ pool2 = reinterpret_cast<const float2*>(g_pool);
    const float4* __restrict__ W4    = reinterpret_cast<const float4*>(W);

    const int kSlice = slice * KSLICE_;

    for (int c = 0; c < 2; ++c) {
        const int k0 = kSlice + c * BKC_;

        // --- load B chunk: W[k0 .. k0+50) x 72, contiguous float4 ---
        {
            float4* Bs4 = reinterpret_cast<float4*>(Bs);
            const float4* src = W4 + (size_t)k0 * (NLAB_ / 4);
            #pragma unroll
            for (int it = 0; it < 29; ++it) {
                int idx = it * 32 + lane;
                if (idx < SL_B_FLOATS_ / 4) Bs4[idx] = src[idx];
            }
        }
        // --- load A chunk: 32 rows x 50 k from g_pool -> As[k][m] ---
        {
            #pragma unroll
            for (int it = 0; it < 25; ++it) {          // 800 float2 total
                int idx = it * 32 + lane;
                int row = idx / 25;                    // 0..31
                int kk  = idx - row * 25;              // float2 index in row
                float2 v = pool2[(size_t)(mBase + row) * D2_ + (k0 >> 1) + kk];
                int l = kk * 2;
                As[(l + 0) * ASTRIDE_ + row] = v.x;
                As[(l + 1) * ASTRIDE_ + row] = v.y;
            }
        }
        __syncwarp();

        // --- mainloop over the 50 local k values ---
        #pragma unroll 2
        for (int l = 0; l < BKC_; ++l) {
            const float* brow = Bs + l * NLAB_ + tn * 9;
            unsigned long long bsp[9];
            #pragma unroll
            for (int j = 0; j < 9; ++j) bsp[j] = splat2(brow[j]);

            const unsigned long long* arow =
                reinterpret_cast<const unsigned long long*>(As + l * ASTRIDE_ + tm * 8);
            unsigned long long av[4];
            #pragma unroll
            for (int mp = 0; mp < 4; ++mp) av[mp] = arow[mp];

            #pragma unroll
            for (int mp = 0; mp < 4; ++mp)
                #pragma unroll
                for (int j = 0; j < 9; ++j)
                    fma2(acc[mp * 9 + j], av[mp], bsp[j]);
        }
        __syncwarp();
    }

    // --- cross-slice reduction (reuse smem; all warps must be done first) ---
    __syncthreads();
    {
        float* red = smem + slice * RED_FLOATS_;      // [32][72] per slice
        #pragma unroll
        for (int mp = 0; mp < 4; ++mp) {
            int m0 = tm * 8 + mp * 2;
            #pragma unroll
            for (int j = 0; j < 9; ++j) {
                float lo, hi;
                unpack2(acc[mp * 9 + j], lo, hi);
                red[(m0 + 0) * NLAB_ + tn * 9 + j] = lo;
                red[(m0 + 1) * NLAB_ + tn * 9 + j] = hi;
            }
        }
    }
    __syncthreads();

    // --- final: each thread sums 9 outputs across 8 slices, adds bias ---
    {
        const int m  = tid >> 3;          // 0..31
        const int ng = tid & 7;           // 0..7
        const int nb = ng * 9;
        #pragma unroll
        for (int j = 0; j < 9; ++j) {
            int n = nb + j;
            float s = 0.0f;
            #pragma unroll
            for (int sl = 0; sl < 8; ++sl)
                s += smem[sl * RED_FLOATS_ + m * NLAB_ + n];
            out[(size_t)(mBase + m) * NLAB_ + n] = s + bias[n];
        }
    }
}

// ---------------------------------------------------------------------------
// Launch wrapper
// Inputs (metadata order): batch_hs f32[64*1024*800], slot_begins i32[64*64],
// slot_lens i32[64*64], W_clf f32[800*72], b_clf f32[72].
// Output: f32[64*64*72].
// ---------------------------------------------------------------------------
extern "C" void kernel_launch(void* const* d_in, const int* in_sizes, int n_in,
                              void* d_out, int out_size)
{
    const float* hs     = (const float*)d_in[0];
    const int*   begins = (const int*)  d_in[1];
    const int*   lens   = (const int*)  d_in[2];
    const float* W      = (const float*)d_in[3];
    const float* bias   = (const float*)d_in[4];
    float*       out    = (float*)d_out;

    // Opt-in to >48KB dynamic smem (attribute set is not a stream op;
    // safe under graph capture, idempotent).
    cudaFuncSetAttribute(gemm_kernel,
                         cudaFuncAttributeMaxDynamicSharedMemorySize,
                         SMEM_BYTES_);

    pool_kernel<<<NPOOL_, 256>>>(hs, begins, lens);
    gemm_kernel<<<NPOOL_ / BM_, 256, SMEM_BYTES_>>>(W, bias, out);
}